// round 5
// baseline (speedup 1.0000x reference)
#include <cuda_runtime.h>
#include <cstdint>

// ---------------- problem constants ----------------
#define NBODY     10
#define NPAIRS    90
#define HID       128
#define TILE      128
#define SELF_ROWS 81920
#define INT_ROWS  737280
#define SELF_TILES (SELF_ROWS / TILE)   // 640
#define INT_TILES  (INT_ROWS / TILE)    // 5760
#define NCTA      148
#define SELF_CTAS 14
#define NTHREADS  512                   // 2 tile-streams of 256 threads
#define S         136                   // smem row stride (floats)

// smem byte offsets
#define OFF_W1T   0          // 128 x S fp32 (tf32-rounded)                69632 B
#define OFF_A0    69632      // stream 0 H0 buffer 128 x S                 69632 B
#define OFF_A1    139264     // stream 1                                   69632 B
#define OFF_P0    208896     // stream 0: inp overlay (4KB) / partials 8KB
#define OFF_P1    217088
#define OFF_W0    225280     // 6*128 fp32
#define OFF_B0    228352     // 128 fp32
#define OFF_B1    228864     // 128 fp32
#define OFF_W2    229376     // 128x4 fp32
#define OFF_B2    231424     // 4 fp32
#define SMEM_TOTAL 231440

__device__ float g_scratch[INT_ROWS * 4];

// ---------------- helpers ----------------
__device__ __forceinline__ float f2tf32f(float x) {
    uint32_t v; asm("cvt.rna.tf32.f32 %0, %1;" : "=r"(v) : "f"(x));
    return __uint_as_float(v);
}
__device__ __forceinline__ float softplus_f(float x) {
    float e, l;
    asm("ex2.approx.f32 %0, %1;" : "=f"(e) : "f"(-fabsf(x) * 1.4426950408889634f));
    asm("lg2.approx.f32 %0, %1;" : "=f"(l) : "f"(1.0f + e));
    return fmaf(l, 0.6931471805599453f, fmaxf(x, 0.0f));
}
// column permutation: words for k-step pair (2K2,2K2+1), cols (j, j+4) contiguous
__device__ __forceinline__ int pos16(int c) {
    return (c & ~15) | ((c & 3) << 2) | (((c >> 3) & 1) << 1) | ((c >> 2) & 1);
}
__device__ __forceinline__ void mma_tf32(float* c, uint32_t a0, uint32_t a1,
                                         uint32_t a2, uint32_t a3,
                                         uint32_t b0, uint32_t b1) {
    asm("mma.sync.aligned.m16n8k8.row.col.f32.tf32.tf32.f32 "
        "{%0,%1,%2,%3}, {%4,%5,%6,%7}, {%8,%9}, {%0,%1,%2,%3};"
        : "+f"(c[0]), "+f"(c[1]), "+f"(c[2]), "+f"(c[3])
        : "r"(a0), "r"(a1), "r"(a2), "r"(a3), "r"(b0), "r"(b1));
}

// ---------------- merged persistent fused MLP ----------------
__global__ __launch_bounds__(NTHREADS, 1)
void mlp_all(const float* __restrict__ z,
             const float* __restrict__ fW0, const float* __restrict__ fb0,
             const float* __restrict__ fW1, const float* __restrict__ fb1,
             const float* __restrict__ fW2, const float* __restrict__ fb2,
             const float* __restrict__ iW0, const float* __restrict__ ib0,
             const float* __restrict__ iW1, const float* __restrict__ ib1,
             const float* __restrict__ iW2, const float* __restrict__ ib2,
             float* __restrict__ out_self)
{
    extern __shared__ __align__(16) char smem[];
    float* W1t = (float*)(smem + OFF_W1T);
    float* W0s = (float*)(smem + OFF_W0);
    float* b0s = (float*)(smem + OFF_B0);
    float* b1s = (float*)(smem + OFF_B1);
    float* b2s = (float*)(smem + OFF_B2);

    const int tid = threadIdx.x;
    const bool self = (blockIdx.x < SELF_CTAS);

    const float *W0, *b0, *W1, *b1, *W2, *b2;
    float* out;
    int ntiles, nstreams, sidx0;
    if (self) {
        W0 = fW0; b0 = fb0; W1 = fW1; b1 = fb1; W2 = fW2; b2 = fb2;
        out = out_self; ntiles = SELF_TILES;
        nstreams = SELF_CTAS * 2; sidx0 = blockIdx.x * 2;
    } else {
        W0 = iW0; b0 = ib0; W1 = iW1; b1 = ib1; W2 = iW2; b2 = ib2;
        out = g_scratch; ntiles = INT_TILES;
        nstreams = (NCTA - SELF_CTAS) * 2; sidx0 = (blockIdx.x - SELF_CTAS) * 2;
    }
    const int NIN = self ? 4 : 6;

    // ---- stage weights once ----
    for (int i = tid; i < HID * HID; i += NTHREADS) {
        int k = i >> 7, n = i & 127;
        W1t[n * S + ((n & 1) << 3) + pos16(k)] = f2tf32f(W1[i]);
    }
    // zero-pad W0 rows 4..5 for self
    for (int i = tid; i < 6 * HID; i += NTHREADS)
        W0s[i] = (i < NIN * HID) ? W0[i] : 0.0f;
    if (tid < HID) { b0s[tid] = b0[tid]; b1s[tid] = b1[tid]; }
    for (int i = tid; i < HID * 4; i += NTHREADS) ((float*)(smem + OFF_W2))[i] = W2[i];
    if (tid < 4) b2s[tid] = b2[tid];
    __syncthreads();

    const int wg   = tid >> 8;            // tile stream 0/1
    const int wt   = tid & 255;
    const int w8   = wt >> 5;             // warp in stream 0..7
    const int lane = tid & 31;
    const int g    = lane >> 2;
    const int j    = lane & 3;
    const int mi   = w8 >> 2;             // rows mi*64..+63
    const int ni   = w8 & 3;              // cols ni*32..+31

    float* As  = (float*)(smem + OFF_A0 + wg * 69632);
    float* P   = (float*)(smem + OFF_P0 + wg * 8192);
    float* inp = P;                       // overlay (dead before P written)
    const int wbar = 1 + wg;

    const float4 b2v = *(const float4*)b2s;

    // ---- layer-0 per-thread constants: column pair (c, c+4), 32 rows ----
    const int pairp = wt & 63;                 // 0..63
    const int rq    = wt >> 6;                 // row quarter 0..3
    const int c0    = (pairp >> 2) * 8 + (pairp & 3);   // c0 % 8 < 4
    const int c1    = c0 + 4;
    float w0a[6], w0b[6];
    #pragma unroll
    for (int q = 0; q < 6; q++) { w0a[q] = W0s[q * HID + c0]; w0b[q] = W0s[q * HID + c1]; }
    const float b0a = b0s[c0], b0b = b0s[c1];
    const int l0dst = rq * 32 * S + pos16(c0); // + r*S + parity within loop

    const int r0 = mi * 64, n0 = ni * 32;
    const int pg = (g & 1) << 3;

    // k-loop base addresses (float indices); everything else is immediate
    const int aBase = (r0 + g) * S + pg + 4 * j;
    const int bBase = (n0 + g) * S + pg + 4 * j;

    for (int t = sidx0 + wg; t < ntiles; t += nstreams) {
        const int rowBase = t * TILE;

        // ---- build 128 input rows ----
        if (wt < 128) {
            int grow = rowBase + wt;
            if (self) {
                float4 zz = ((const float4*)z)[grow];
                *(float4*)&inp[wt * 8]     = zz;
                *(float4*)&inp[wt * 8 + 4] = make_float4(0.f, 0.f, 0.f, 0.f);
            } else {
                int n   = grow / NPAIRS;
                int pr  = grow - n * NPAIRS;
                int rec = pr / (NBODY - 1);
                int sr  = pr - rec * (NBODY - 1);
                int snd = sr + (sr >= rec ? 1 : 0);
                float4 zr = ((const float4*)z)[n * NBODY + rec];
                float4 zs = ((const float4*)z)[n * NBODY + snd];
                *(float4*)&inp[wt * 8]     = make_float4(zr.x - zs.x, zr.y - zs.y, zr.z, zr.w);
                *(float4*)&inp[wt * 8 + 4] = make_float4(zs.z, zs.w, 0.0f, 0.0f);
            }
        }
        asm volatile("bar.sync %0, 256;" :: "r"(wbar) : "memory");

        // ---- layer 0: cols (c0, c1) for 32 rows ----
        #pragma unroll 4
        for (int r = 0; r < 32; r++) {
            const int row = rq * 32 + r;
            float4 i0 = *(const float4*)&inp[row * 8];
            float4 i1 = *(const float4*)&inp[row * 8 + 4];
            float a = b0a, b = b0b;
            a = fmaf(i0.x, w0a[0], a);  b = fmaf(i0.x, w0b[0], b);
            a = fmaf(i0.y, w0a[1], a);  b = fmaf(i0.y, w0b[1], b);
            a = fmaf(i0.z, w0a[2], a);  b = fmaf(i0.z, w0b[2], b);
            a = fmaf(i0.w, w0a[3], a);  b = fmaf(i0.w, w0b[3], b);
            a = fmaf(i1.x, w0a[4], a);  b = fmaf(i1.x, w0b[4], b);
            a = fmaf(i1.y, w0a[5], a);  b = fmaf(i1.y, w0b[5], b);
            float2 hv = make_float2(f2tf32f(softplus_f(a)), f2tf32f(softplus_f(b)));
            *(float2*)&As[l0dst + r * S + ((row & 1) << 3)] = hv;
        }
        asm volatile("bar.sync %0, 256;" :: "r"(wbar) : "memory");

        // ---- layer 1: 64x32 warp tile, paired-k LDS.128, immediate offsets ----
        float c[4][4][4];
        #pragma unroll
        for (int mt = 0; mt < 4; mt++)
            #pragma unroll
            for (int nt = 0; nt < 4; nt++)
                #pragma unroll
                for (int q = 0; q < 4; q++) c[mt][nt][q] = 0.0f;

        #pragma unroll
        for (int K2 = 0; K2 < 8; K2++) {
            uint4 bv[4];
            #pragma unroll
            for (int nt = 0; nt < 4; nt++)
                bv[nt] = *(const uint4*)&W1t[bBase + nt * 8 * S + K2 * 16];
            #pragma unroll
            for (int mh = 0; mh < 2; mh++) {
                uint4 al[2], ah[2];
                #pragma unroll
                for (int m2 = 0; m2 < 2; m2++) {
                    const int mo = (mh * 2 + m2) * 16 * S + K2 * 16;
                    al[m2] = *(const uint4*)&As[aBase + mo];
                    ah[m2] = *(const uint4*)&As[aBase + mo + 8 * S];
                }
                #pragma unroll
                for (int m2 = 0; m2 < 2; m2++)
                    #pragma unroll
                    for (int nt = 0; nt < 4; nt++) {
                        mma_tf32(c[mh * 2 + m2][nt],
                                 al[m2].x, ah[m2].x, al[m2].y, ah[m2].y,
                                 bv[nt].x, bv[nt].y);
                        mma_tf32(c[mh * 2 + m2][nt],
                                 al[m2].z, ah[m2].z, al[m2].w, ah[m2].w,
                                 bv[nt].z, bv[nt].w);
                    }
            }
        }

        // ---- epilogue: h1 = softplus(D + b1); partial = h1 @ W2 ----
        float  b1r[8];
        float4 w2r[8];
        #pragma unroll
        for (int nt = 0; nt < 4; nt++)
            #pragma unroll
            for (int kk = 0; kk < 2; kk++) {
                int cc = n0 + nt * 8 + 2 * j + kk;
                b1r[nt * 2 + kk] = b1s[cc];
                w2r[nt * 2 + kk] = ((const float4*)(smem + OFF_W2))[cc];
            }
        #pragma unroll
        for (int mt = 0; mt < 4; mt++) {
            #pragma unroll
            for (int rr = 0; rr < 2; rr++) {
                float4 p = make_float4(0.f, 0.f, 0.f, 0.f);
                #pragma unroll
                for (int nt = 0; nt < 4; nt++)
                    #pragma unroll
                    for (int kk = 0; kk < 2; kk++) {
                        float h = softplus_f(c[mt][nt][rr * 2 + kk] + b1r[nt * 2 + kk]);
                        float4 wv = w2r[nt * 2 + kk];
                        p.x = fmaf(h, wv.x, p.x); p.y = fmaf(h, wv.y, p.y);
                        p.z = fmaf(h, wv.z, p.z); p.w = fmaf(h, wv.w, p.w);
                    }
                #pragma unroll
                for (int msk = 1; msk <= 2; msk <<= 1) {
                    p.x += __shfl_xor_sync(0xffffffffu, p.x, msk);
                    p.y += __shfl_xor_sync(0xffffffffu, p.y, msk);
                    p.z += __shfl_xor_sync(0xffffffffu, p.z, msk);
                    p.w += __shfl_xor_sync(0xffffffffu, p.w, msk);
                }
                if (j == 0) {
                    int row = r0 + mt * 16 + rr * 8 + g;
                    *(float4*)&P[(ni * 128 + row) * 4] = p;
                }
            }
        }
        asm volatile("bar.sync %0, 256;" :: "r"(wbar) : "memory");

        if (wt < 128) {
            const float4* P4 = (const float4*)P;
            float4 o4 = b2v;
            #pragma unroll
            for (int q = 0; q < 4; q++) {
                float4 v = P4[q * 128 + wt];
                o4.x += v.x; o4.y += v.y; o4.z += v.z; o4.w += v.w;
            }
            ((float4*)out)[rowBase + wt] = o4;
        }
        asm volatile("bar.sync %0, 256;" :: "r"(wbar) : "memory");
    }
}

// out[n,rec,:] += sum_{j} scratch[n*90 + rec*9 + j, :]
__global__ void reduce_kernel(float* __restrict__ out)
{
    int r = blockIdx.x * blockDim.x + threadIdx.x;
    if (r >= SELF_ROWS) return;
    int n = r / NBODY, rec = r - n * NBODY;
    const float4* sc = (const float4*)g_scratch;
    int base = n * NPAIRS + rec * (NBODY - 1);
    float4 s = sc[base];
    #pragma unroll
    for (int q = 1; q < NBODY - 1; q++) {
        float4 v = sc[base + q];
        s.x += v.x; s.y += v.y; s.z += v.z; s.w += v.w;
    }
    float4 o = ((float4*)out)[r];
    o.x += s.x; o.y += s.y; o.z += s.z; o.w += s.w;
    ((float4*)out)[r] = o;
}

extern "C" void kernel_launch(void* const* d_in, const int* in_sizes, int n_in,
                              void* d_out, int out_size)
{
    const float* z   = (const float*)d_in[0];
    const float* fW0 = (const float*)d_in[1];
    const float* fb0 = (const float*)d_in[2];
    const float* fW1 = (const float*)d_in[3];
    const float* fb1 = (const float*)d_in[4];
    const float* fW2 = (const float*)d_in[5];
    const float* fb2 = (const float*)d_in[6];
    const float* iW0 = (const float*)d_in[7];
    const float* ib0 = (const float*)d_in[8];
    const float* iW1 = (const float*)d_in[9];
    const float* ib1 = (const float*)d_in[10];
    const float* iW2 = (const float*)d_in[11];
    const float* ib2 = (const float*)d_in[12];
    float* out = (float*)d_out;

    cudaFuncSetAttribute(mlp_all, cudaFuncAttributeMaxDynamicSharedMemorySize, SMEM_TOTAL);

    mlp_all<<<NCTA, NTHREADS, SMEM_TOTAL>>>(z, fW0, fb0, fW1, fb1, fW2, fb2,
                                            iW0, ib0, iW1, ib1, iW2, ib2, out);
    reduce_kernel<<<(SELF_ROWS + 255) / 256, 256>>>(out);
}

// round 6
// speedup vs baseline: 1.3694x; 1.3694x over previous
#include <cuda_runtime.h>
#include <cstdint>

// ---------------- problem constants ----------------
#define NBODY     10
#define NPAIRS    90
#define HID       128
#define TILE      128
#define SELF_ROWS 81920
#define INT_ROWS  737280
#define SELF_TILES (SELF_ROWS / TILE)   // 640
#define INT_TILES  (INT_ROWS / TILE)    // 5760
#define NCTA      148
#define NTHREADS  512                   // 2 tile-streams of 256 threads
#define S         136                   // smem row stride (floats): conflict-free frags

// smem byte offsets (identical to R3)
#define OFF_W1T   0          // 128 x S fp32 (tf32-rounded), [n][pos(k)]   69632 B
#define OFF_A0    69632      // tile-stream 0 H0 buffer 128 x S            69632 B
#define OFF_A1    139264     // tile-stream 1                              69632 B
#define OFF_P0    208896     // stream 0: inp overlay (4KB) / partials 8KB
#define OFF_P1    217088
#define OFF_W0    225280     // 6*128 fp32 (zero-padded)
#define OFF_B0    228352     // 128 fp32
#define OFF_B1    228864     // 128 fp32
#define OFF_W2    229376     // 128x4 fp32
#define OFF_B2    231424     // 4 fp32
#define SMEM_TOTAL 231456

__device__ float g_scratch[INT_ROWS * 4];

// ---------------- helpers ----------------
__device__ __forceinline__ float f2tf32f(float x) {
    uint32_t v; asm("cvt.rna.tf32.f32 %0, %1;" : "=r"(v) : "f"(x));
    return __uint_as_float(v);
}
__device__ __forceinline__ float softplus_f(float x) {
    float e = __expf(-fabsf(x));
    return fmaxf(x, 0.0f) + __logf(1.0f + e);
}
// permute cols within each 8-group so (c, c+4) are adjacent: frag loads = uint2
__device__ __forceinline__ int pos8(int c) {
    return (c & ~7) | ((c & 3) << 1) | ((c >> 2) & 1);
}
__device__ __forceinline__ void mma_tf32(float* c, uint32_t a0, uint32_t a1,
                                         uint32_t a2, uint32_t a3,
                                         uint32_t b0, uint32_t b1) {
    asm("mma.sync.aligned.m16n8k8.row.col.f32.tf32.tf32.f32 "
        "{%0,%1,%2,%3}, {%4,%5,%6,%7}, {%8,%9}, {%0,%1,%2,%3};"
        : "+f"(c[0]), "+f"(c[1]), "+f"(c[2]), "+f"(c[3])
        : "r"(a0), "r"(a1), "r"(a2), "r"(a3), "r"(b0), "r"(b1));
}

// ---------------- two-phase persistent fused MLP ----------------
__global__ __launch_bounds__(NTHREADS, 1)
void mlp_all(const float* __restrict__ z,
             const float* __restrict__ fW0, const float* __restrict__ fb0,
             const float* __restrict__ fW1, const float* __restrict__ fb1,
             const float* __restrict__ fW2, const float* __restrict__ fb2,
             const float* __restrict__ iW0, const float* __restrict__ ib0,
             const float* __restrict__ iW1, const float* __restrict__ ib1,
             const float* __restrict__ iW2, const float* __restrict__ ib2,
             float* __restrict__ out_self)
{
    extern __shared__ __align__(16) char smem[];
    float* W1t = (float*)(smem + OFF_W1T);
    float* W0s = (float*)(smem + OFF_W0);
    float* b0s = (float*)(smem + OFF_B0);
    float* b1s = (float*)(smem + OFF_B1);
    const float4* W2v = (const float4*)(smem + OFF_W2);
    float* b2s = (float*)(smem + OFF_B2);

    const int tid = threadIdx.x;

    const int wg   = tid >> 8;            // tile stream 0/1
    const int wt   = tid & 255;
    const int w8   = wt >> 5;             // warp in stream: 0..7
    const int lane = tid & 31;
    const int g    = lane >> 2;           // frag group row
    const int j    = lane & 3;            // frag thread-in-group
    const int mi   = w8 >> 2;             // 0/1: rows mi*64..+63
    const int ni   = w8 & 3;              // 0..3: cols ni*32..+31

    float* As  = (float*)(smem + OFF_A0 + wg * 69632);
    float* P   = (float*)(smem + OFF_P0 + wg * 8192);
    float* inp = P;                       // overlay: dead before partials are written
    const int wbar = 1 + wg;

    // layer0 thread mapping (thread = column col, row-half wt>>7)
    const int col   = wt & 127;
    const int rbase = (wt >> 7) * 64;
    const int pc    = pos8(col);
    const int r0 = mi * 64, n0 = ni * 32;

    #pragma unroll 1
    for (int phase = 0; phase < 2; phase++) {
        const bool isSelf = (phase == 1);
        const float* W0 = isSelf ? fW0 : iW0;
        const float* b0 = isSelf ? fb0 : ib0;
        const float* W1 = isSelf ? fW1 : iW1;
        const float* b1 = isSelf ? fb1 : ib1;
        const float* W2 = isSelf ? fW2 : iW2;
        const float* b2 = isSelf ? fb2 : ib2;
        float* out = isSelf ? out_self : g_scratch;
        const int ntiles = isSelf ? SELF_TILES : INT_TILES;
        const int NIN = isSelf ? 4 : 6;

        // ---- stage weights for this phase ----
        for (int i = tid; i < HID * HID; i += NTHREADS) {
            int k = i >> 7, n = i & 127;
            W1t[n * S + pos8(k)] = f2tf32f(W1[i]);   // B as [n][pos(k)]
        }
        for (int i = tid; i < 6 * HID; i += NTHREADS)
            W0s[i] = (i < NIN * HID) ? W0[i] : 0.0f;
        if (tid < HID) { b0s[tid] = b0[tid]; b1s[tid] = b1[tid]; }
        for (int i = tid; i < HID * 4; i += NTHREADS)
            ((float*)(smem + OFF_W2))[i] = W2[i];
        if (tid < 4) b2s[tid] = b2[tid];
        __syncthreads();

        const float4 b2v = *(const float4*)b2s;
        float w0r[6];
        #pragma unroll
        for (int q = 0; q < 6; q++) w0r[q] = W0s[q * HID + col];
        const float b0c = b0s[col];

        for (int t = blockIdx.x * 2 + wg; t < ntiles; t += gridDim.x * 2) {
            const int rowBase = t * TILE;

            // ---- build 128 input rows ----
            if (wt < 128) {
                int grow = rowBase + wt;
                if (isSelf) {
                    float4 zz = ((const float4*)z)[grow];
                    *(float4*)&inp[wt * 8]     = zz;
                    *(float4*)&inp[wt * 8 + 4] = make_float4(0.f, 0.f, 0.f, 0.f);
                } else {
                    int n   = grow / NPAIRS;
                    int pr  = grow - n * NPAIRS;
                    int rec = pr / (NBODY - 1);
                    int sr  = pr - rec * (NBODY - 1);
                    int snd = sr + (sr >= rec ? 1 : 0);
                    float4 zr = ((const float4*)z)[n * NBODY + rec];
                    float4 zs = ((const float4*)z)[n * NBODY + snd];
                    *(float4*)&inp[wt * 8]     = make_float4(zr.x - zs.x, zr.y - zs.y, zr.z, zr.w);
                    *(float4*)&inp[wt * 8 + 4] = make_float4(zs.z, zs.w, 0.0f, 0.0f);
                }
            }
            asm volatile("bar.sync %0, 256;" :: "r"(wbar) : "memory");

            // ---- layer 0: As[r][pos(col)] = tf32(softplus(inp[r].W0[:,col]+b0)) ----
            #pragma unroll 4
            for (int r = 0; r < 64; r++) {
                float4 i0 = *(const float4*)&inp[(rbase + r) * 8];
                float4 i1 = *(const float4*)&inp[(rbase + r) * 8 + 4];
                float a = b0c;
                a = fmaf(i0.x, w0r[0], a); a = fmaf(i0.y, w0r[1], a);
                a = fmaf(i0.z, w0r[2], a); a = fmaf(i0.w, w0r[3], a);
                a = fmaf(i1.x, w0r[4], a); a = fmaf(i1.y, w0r[5], a);
                As[(rbase + r) * S + pc] = f2tf32f(softplus_f(a));
            }
            asm volatile("bar.sync %0, 256;" :: "r"(wbar) : "memory");

            // ---- layer 1: 64x32 warp tile, m16n8k8 tf32 (R3-exact) ----
            float c[4][4][4];
            #pragma unroll
            for (int mt = 0; mt < 4; mt++)
                #pragma unroll
                for (int nt = 0; nt < 4; nt++)
                    #pragma unroll
                    for (int q = 0; q < 4; q++) c[mt][nt][q] = 0.0f;

            #pragma unroll 1
            for (int k = 0; k < 16; k++) {
                const int kb = k * 8 + 2 * j;
                uint2 bf[4], a0v[4], a1v[4];
                #pragma unroll
                for (int nt = 0; nt < 4; nt++)
                    bf[nt] = *(const uint2*)&W1t[(n0 + nt * 8 + g) * S + kb];
                #pragma unroll
                for (int mt = 0; mt < 4; mt++) {
                    a0v[mt] = *(const uint2*)&As[(r0 + mt * 16 + g) * S + kb];
                    a1v[mt] = *(const uint2*)&As[(r0 + mt * 16 + 8 + g) * S + kb];
                }
                #pragma unroll
                for (int mt = 0; mt < 4; mt++)
                    #pragma unroll
                    for (int nt = 0; nt < 4; nt++)
                        mma_tf32(c[mt][nt], a0v[mt].x, a1v[mt].x, a0v[mt].y, a1v[mt].y,
                                 bf[nt].x, bf[nt].y);
            }

            // ---- epilogue: h1 = softplus(D + b1); partial = h1 @ W2 ----
            float  b1r[8];
            float4 w2r[8];
            #pragma unroll
            for (int nt = 0; nt < 4; nt++)
                #pragma unroll
                for (int kk = 0; kk < 2; kk++) {
                    int cc = n0 + nt * 8 + 2 * j + kk;
                    b1r[nt * 2 + kk] = b1s[cc];
                    w2r[nt * 2 + kk] = W2v[cc];
                }
            #pragma unroll
            for (int mt = 0; mt < 4; mt++) {
                #pragma unroll
                for (int rr = 0; rr < 2; rr++) {
                    float4 p = make_float4(0.f, 0.f, 0.f, 0.f);
                    #pragma unroll
                    for (int nt = 0; nt < 4; nt++)
                        #pragma unroll
                        for (int kk = 0; kk < 2; kk++) {
                            float h = softplus_f(c[mt][nt][rr * 2 + kk] + b1r[nt * 2 + kk]);
                            float4 wv = w2r[nt * 2 + kk];
                            p.x = fmaf(h, wv.x, p.x); p.y = fmaf(h, wv.y, p.y);
                            p.z = fmaf(h, wv.z, p.z); p.w = fmaf(h, wv.w, p.w);
                        }
                    #pragma unroll
                    for (int msk = 1; msk <= 2; msk <<= 1) {
                        p.x += __shfl_xor_sync(0xffffffffu, p.x, msk);
                        p.y += __shfl_xor_sync(0xffffffffu, p.y, msk);
                        p.z += __shfl_xor_sync(0xffffffffu, p.z, msk);
                        p.w += __shfl_xor_sync(0xffffffffu, p.w, msk);
                    }
                    if (j == 0) {
                        int row = r0 + mt * 16 + rr * 8 + g;
                        *(float4*)&P[(ni * 128 + row) * 4] = p;
                    }
                }
            }
            asm volatile("bar.sync %0, 256;" :: "r"(wbar) : "memory");

            if (wt < 128) {
                const float4* P4 = (const float4*)P;
                float4 o4 = b2v;
                #pragma unroll
                for (int q = 0; q < 4; q++) {
                    float4 v = P4[q * 128 + wt];
                    o4.x += v.x; o4.y += v.y; o4.z += v.z; o4.w += v.w;
                }
                ((float4*)out)[rowBase + wt] = o4;
            }
            asm volatile("bar.sync %0, 256;" :: "r"(wbar) : "memory");
        }
        __syncthreads();   // both streams done before restaging weights
    }
}

// out[n,rec,:] += sum_{j} scratch[n*90 + rec*9 + j, :]
__global__ void reduce_kernel(float* __restrict__ out)
{
    int r = blockIdx.x * blockDim.x + threadIdx.x;
    if (r >= SELF_ROWS) return;
    int n = r / NBODY, rec = r - n * NBODY;
    const float4* sc = (const float4*)g_scratch;
    int base = n * NPAIRS + rec * (NBODY - 1);
    float4 s = sc[base];
    #pragma unroll
    for (int q = 1; q < NBODY - 1; q++) {
        float4 v = sc[base + q];
        s.x += v.x; s.y += v.y; s.z += v.z; s.w += v.w;
    }
    float4 o = ((float4*)out)[r];
    o.x += s.x; o.y += s.y; o.z += s.z; o.w += s.w;
    ((float4*)out)[r] = o;
}

extern "C" void kernel_launch(void* const* d_in, const int* in_sizes, int n_in,
                              void* d_out, int out_size)
{
    const float* z   = (const float*)d_in[0];
    const float* fW0 = (const float*)d_in[1];
    const float* fb0 = (const float*)d_in[2];
    const float* fW1 = (const float*)d_in[3];
    const float* fb1 = (const float*)d_in[4];
    const float* fW2 = (const float*)d_in[5];
    const float* fb2 = (const float*)d_in[6];
    const float* iW0 = (const float*)d_in[7];
    const float* ib0 = (const float*)d_in[8];
    const float* iW1 = (const float*)d_in[9];
    const float* ib1 = (const float*)d_in[10];
    const float* iW2 = (const float*)d_in[11];
    const float* ib2 = (const float*)d_in[12];
    float* out = (float*)d_out;

    cudaFuncSetAttribute(mlp_all, cudaFuncAttributeMaxDynamicSharedMemorySize, SMEM_TOTAL);

    mlp_all<<<NCTA, NTHREADS, SMEM_TOTAL>>>(z, fW0, fb0, fW1, fb1, fW2, fb2,
                                            iW0, ib0, iW1, ib1, iW2, ib2, out);
    reduce_kernel<<<(SELF_ROWS + 255) / 256, 256>>>(out);
}